// round 14
// baseline (speedup 1.0000x reference)
#include <cuda_runtime.h>
#include <cuda_fp16.h>
#include <math.h>
#include <stdint.h>

// ---------------- problem constants ----------------
#define T_TOKENS 100352      // 8 * 112 * 112
#define C_DIM    256
#define HID      1024
#define QKV_DIM  768
#define IMG      112
#define WS7      7
#define TOK_PER_IMG 12544

#define W_QKV_ELEMS  (QKV_DIM * C_DIM)
#define W_PROJ_ELEMS (C_DIM * C_DIM)
#define W_FC1_ELEMS  (HID * C_DIM)
#define W_FC2_ELEMS  (C_DIM * HID)
#define W_TOTAL (W_QKV_ELEMS + W_PROJ_ELEMS + W_FC1_ELEMS + W_FC2_ELEMS)

// ---------------- scratch ----------------
__device__ __align__(16) __half g_a  [(size_t)T_TOKENS * C_DIM];
__device__ __align__(16) __half g_b  [(size_t)T_TOKENS * HID];
__device__ __align__(16) __half g_w  [(size_t)W_TOTAL];
__device__ __align__(16) float  g_qkv[(size_t)T_TOKENS * QKV_DIM];
__device__ __align__(16) float  g_x2 [(size_t)T_TOKENS * C_DIM];

// ---------------- helpers ----------------
__device__ __forceinline__ uint32_t smem_u32(const void* p) {
    uint32_t a;
    asm("{ .reg .u64 t; cvta.to.shared.u64 t, %1; cvt.u32.u64 %0, t; }"
        : "=r"(a) : "l"(p));
    return a;
}
__device__ __forceinline__ uint32_t h2pack(float a, float b) {
    __half2 t = __floats2half2_rn(a, b);
    return *reinterpret_cast<uint32_t*>(&t);
}
__device__ __forceinline__ void cp16(uint32_t dst, const void* src) {
    asm volatile("cp.async.cg.shared.global [%0], [%1], 16;"
                 :: "r"(dst), "l"(src) : "memory");
}
__device__ __forceinline__ void cp_commit() {
    asm volatile("cp.async.commit_group;" ::: "memory");
}
__device__ __forceinline__ void cp_wait1() {
    asm volatile("cp.async.wait_group 1;" ::: "memory");
}
__device__ __forceinline__ void cp_wait0() {
    asm volatile("cp.async.wait_group 0;" ::: "memory");
}
#define LDM4(r, addr) \
    asm volatile("ldmatrix.sync.aligned.m8n8.x4.shared.b16 {%0,%1,%2,%3}, [%4];" \
        : "=r"((r)[0]), "=r"((r)[1]), "=r"((r)[2]), "=r"((r)[3]) : "r"(addr))
#define MMA(d, a, b) \
    asm volatile("mma.sync.aligned.m16n8k16.row.col.f32.f16.f16.f32 " \
        "{%0,%1,%2,%3}, {%4,%5,%6,%7}, {%8,%9}, {%0,%1,%2,%3};" \
        : "+f"((d)[0]), "+f"((d)[1]), "+f"((d)[2]), "+f"((d)[3]) \
        : "r"((a)[0]), "r"((a)[1]), "r"((a)[2]), "r"((a)[3]), \
          "r"((b)[0]), "r"((b)[1]))

// ---------------- fused weight convert fp32 -> fp16 (all 4 weights) ----------------
__global__ void wconv_all_kernel(const float* __restrict__ w0,
                                 const float* __restrict__ w1,
                                 const float* __restrict__ w2,
                                 const float* __restrict__ w3,
                                 __half* __restrict__ h) {
    int i = (blockIdx.x * 256 + threadIdx.x) * 4;
    const float* src;
    int off;
    if (i < W_QKV_ELEMS)                                   { src = w0; off = i; }
    else if (i < W_QKV_ELEMS + W_PROJ_ELEMS)               { src = w1; off = i - W_QKV_ELEMS; }
    else if (i < W_QKV_ELEMS + W_PROJ_ELEMS + W_FC1_ELEMS) { src = w2; off = i - W_QKV_ELEMS - W_PROJ_ELEMS; }
    else                                                   { src = w3; off = i - W_QKV_ELEMS - W_PROJ_ELEMS - W_FC1_ELEMS; }
    float4 v = *(const float4*)(src + off);
    *(uint2*)(h + i) = make_uint2(h2pack(v.x, v.y), h2pack(v.z, v.w));
}

// ---------------- LayerNorm -> fp16 ----------------
__global__ void ln_h_kernel(const float* __restrict__ x,
                            const float* __restrict__ gamma,
                            const float* __restrict__ beta,
                            __half* __restrict__ oh) {
    int row  = blockIdx.x * 8 + (threadIdx.x >> 5);
    int lane = threadIdx.x & 31;
    const float4* xr = (const float4*)(x + (size_t)row * C_DIM);
    float4 v0 = xr[lane];
    float4 v1 = xr[lane + 32];
    float s  = v0.x + v0.y + v0.z + v0.w + v1.x + v1.y + v1.z + v1.w;
    float s2 = v0.x*v0.x + v0.y*v0.y + v0.z*v0.z + v0.w*v0.w
             + v1.x*v1.x + v1.y*v1.y + v1.z*v1.z + v1.w*v1.w;
    #pragma unroll
    for (int o = 16; o > 0; o >>= 1) {
        s  += __shfl_xor_sync(0xffffffffu, s,  o);
        s2 += __shfl_xor_sync(0xffffffffu, s2, o);
    }
    float mean = s * (1.f / 256.f);
    float var  = s2 * (1.f / 256.f) - mean * mean;
    float inv  = rsqrtf(var + 1e-5f);

    const float4* gr = (const float4*)gamma;
    const float4* br = (const float4*)beta;
    float4 g0 = gr[lane], g1v = gr[lane + 32];
    float4 b0 = br[lane], b1v = br[lane + 32];
    float o0[4], o1[4];
    o0[0] = (v0.x - mean) * inv * g0.x + b0.x;
    o0[1] = (v0.y - mean) * inv * g0.y + b0.y;
    o0[2] = (v0.z - mean) * inv * g0.z + b0.z;
    o0[3] = (v0.w - mean) * inv * g0.w + b0.w;
    o1[0] = (v1.x - mean) * inv * g1v.x + b1v.x;
    o1[1] = (v1.y - mean) * inv * g1v.y + b1v.y;
    o1[2] = (v1.z - mean) * inv * g1v.z + b1v.z;
    o1[3] = (v1.w - mean) * inv * g1v.w + b1v.w;

    size_t base = (size_t)row * C_DIM;
    *(uint2*)(oh + base + lane * 4)       = make_uint2(h2pack(o0[0], o0[1]), h2pack(o0[2], o0[3]));
    *(uint2*)(oh + base + 128 + lane * 4) = make_uint2(h2pack(o1[0], o1[1]), h2pack(o1[2], o1[3]));
}

// ---------------- mma.sync GEMM: C[M,N] = A[M,K] @ W[N,K]^T ----------------
// 128x128 CTA tile, 4 warps (2m x 2n), warp tile 64x64, BK=64, 2-stage
// cp.async pipeline (72KB smem -> 2 CTA/SM), count-correct tail,
// register fragment double-buffering.
// EPI: 0 = bias -> fp32; 1 = bias + residual -> fp32; 2 = bias + GELU -> fp16
#define ARR_BYTES 18432
#define STG_BYTES 36864
#define GEMM_SMEM (2 * STG_BYTES)

template<int EPI>
__global__ __launch_bounds__(128, 2)
void gemm_mma(const __half* __restrict__ A,
              const __half* __restrict__ W,
              const float* __restrict__ bias,
              const float* __restrict__ res,
              float* __restrict__ outf,
              __half* __restrict__ outh,
              int N, int K) {
    extern __shared__ char smem[];
    uint32_t sb = smem_u32(smem);
    int tid  = threadIdx.x;
    int lane = tid & 31, w = tid >> 5;
    int wm = w >> 1, wn = w & 1;
    int m0 = blockIdx.y * 128, n0 = blockIdx.x * 128;
    const int NCH = K >> 6;

    float acc[4][8][4];
    #pragma unroll
    for (int mt = 0; mt < 4; mt++)
        #pragma unroll
        for (int nt = 0; nt < 8; nt++)
            #pragma unroll
            for (int q = 0; q < 4; q++) acc[mt][nt][q] = 0.f;

    #define ISSUE_CHUNK(ch) do {                                               \
        int k0i = (ch) << 6;                                                   \
        uint32_t stb = sb + ((ch) & 1) * STG_BYTES;                            \
        _Pragma("unroll")                                                      \
        for (int i = 0; i < 16; i++) {                                         \
            int idx = i * 128 + tid;                                           \
            int arr = idx >> 10;                                               \
            int rem = idx & 1023;                                              \
            int r = rem >> 3, c = rem & 7;                                     \
            const __half* s = (arr ? W + (size_t)(n0 + r) * K                  \
                                   : A + (size_t)(m0 + r) * K) + k0i + c * 8;  \
            cp16(stb + arr * ARR_BYTES + r * 144 + c * 16, s);                 \
        }                                                                      \
        cp_commit();                                                           \
    } while (0)

    ISSUE_CHUNK(0);

    int arow = wm * 64 + (lane & 15);
    uint32_t aoff = (uint32_t)arow * 144 + ((lane & 16) ? 16u : 0u);
    int brow = wn * 64 + (lane & 7) + ((lane & 16) ? 8 : 0);
    uint32_t boff = (uint32_t)brow * 144 + ((lane & 8) ? 16u : 0u);

    uint32_t ah[2][4][4], bh[2][8][2];

    #define LOAD_FRAGS(kk_, b_, As_, Ws_) do {                                 \
        uint32_t akb = (kk_) * 32;                                             \
        _Pragma("unroll")                                                      \
        for (int mt = 0; mt < 4; mt++)                                         \
            LDM4(ah[b_][mt], (As_) + aoff + (uint32_t)(mt * 16) * 144 + akb);  \
        _Pragma("unroll")                                                      \
        for (int p = 0; p < 4; p++) {                                          \
            uint32_t t[4];                                                     \
            LDM4(t, (Ws_) + boff + (uint32_t)(p * 16) * 144 + akb);            \
            bh[b_][2*p][0] = t[0]; bh[b_][2*p][1] = t[1];                      \
            bh[b_][2*p+1][0] = t[2]; bh[b_][2*p+1][1] = t[3];                  \
        }                                                                      \
    } while (0)

    for (int ch = 0; ch < NCH; ch++) {
        if (ch + 1 < NCH) { ISSUE_CHUNK(ch + 1); cp_wait1(); }
        else cp_wait0();
        __syncthreads();

        uint32_t As = sb + (ch & 1) * STG_BYTES;
        uint32_t Ws = As + ARR_BYTES;

        LOAD_FRAGS(0, 0, As, Ws);
        #pragma unroll
        for (int kk = 0; kk < 4; kk++) {
            int cur = kk & 1;
            if (kk < 3) LOAD_FRAGS(kk + 1, cur ^ 1, As, Ws);
            #pragma unroll
            for (int mt = 0; mt < 4; mt++)
                #pragma unroll
                for (int nt = 0; nt < 8; nt++)
                    MMA(acc[mt][nt], ah[cur][mt], bh[cur][nt]);
        }
        __syncthreads();
    }

    // ---- epilogue: registers -> global ----
    int lg = lane >> 2, lt = lane & 3;
    #pragma unroll
    for (int mt = 0; mt < 4; mt++) {
        #pragma unroll
        for (int h = 0; h < 2; h++) {
            size_t m = (size_t)(m0 + wm * 64 + mt * 16 + lg + h * 8);
            #pragma unroll
            for (int nt = 0; nt < 8; nt++) {
                int n = n0 + wn * 64 + nt * 8 + lt * 2;
                float2 bv = *(const float2*)(bias + n);
                float v0 = acc[mt][nt][h * 2 + 0] + bv.x;
                float v1 = acc[mt][nt][h * 2 + 1] + bv.y;
                if (EPI == 0) {
                    *(float2*)(outf + m * N + n) = make_float2(v0, v1);
                } else if (EPI == 1) {
                    float2 rr = *(const float2*)(res + m * N + n);
                    *(float2*)(outf + m * N + n) = make_float2(v0 + rr.x, v1 + rr.y);
                } else {
                    v0 = 0.5f * v0 * (1.f + erff(v0 * 0.7071067811865476f));
                    v1 = 0.5f * v1 * (1.f + erff(v1 * 0.7071067811865476f));
                    *(uint32_t*)(outh + m * N + n) = h2pack(v0, v1);
                }
            }
        }
    }
    #undef ISSUE_CHUNK
    #undef LOAD_FRAGS
}

// ---------------- fused window attention (fp32 qkv) -> fp16 ----------------
// R14: K/V smem reads vectorized to float4 (broadcast, conflict-free, 4x fewer
// LDS issues) and scores kept in registers (ss smem array eliminated).
__global__ void attn_kernel(const float* __restrict__ qkv,
                            __half* __restrict__ oh) {
    __shared__ float ks[49][32];
    __shared__ float vs[49][32];
    __shared__ int   tok[49];

    int head = blockIdx.x & 7;
    int win  = blockIdx.x >> 3;
    int n    = win >> 8;
    int wrem = win & 255;
    int wr   = wrem >> 4;
    int wc   = wrem & 15;
    int tid  = threadIdx.x;

    if (tid < 49) {
        int hh = wr * WS7 + tid / 7;
        int ww = wc * WS7 + tid % 7;
        tok[tid] = n * TOK_PER_IMG + hh * IMG + ww;
    }
    __syncthreads();

    int cb = head * 32;
    for (int i = tid; i < 49 * 8; i += 64) {
        int rowi = i >> 3;
        int c4   = (i & 7) * 4;
        const float* base = qkv + (size_t)tok[rowi] * QKV_DIM;
        *(float4*)&ks[rowi][c4] = *(const float4*)(base + C_DIM     + cb + c4);
        *(float4*)&vs[rowi][c4] = *(const float4*)(base + 2 * C_DIM + cb + c4);
    }
    __syncthreads();

    if (tid < 49) {
        float qr[32];
        const float* qb = qkv + (size_t)tok[tid] * QKV_DIM + cb;
        #pragma unroll
        for (int dd = 0; dd < 32; dd += 4) {
            float4 v = *(const float4*)(qb + dd);
            qr[dd] = v.x; qr[dd + 1] = v.y; qr[dd + 2] = v.z; qr[dd + 3] = v.w;
        }
        const float scale = 0.17677669529663687f;
        float sc[49];
        float mx = -1e30f;
        #pragma unroll 7
        for (int m = 0; m < 49; m++) {
            float d = 0.f;
            #pragma unroll
            for (int dd = 0; dd < 32; dd += 4) {
                float4 kf = *(const float4*)&ks[m][dd];
                d += qr[dd] * kf.x + qr[dd + 1] * kf.y
                   + qr[dd + 2] * kf.z + qr[dd + 3] * kf.w;
            }
            d *= scale;
            sc[m] = d;
            mx = fmaxf(mx, d);
        }
        float sum = 0.f;
        #pragma unroll
        for (int m = 0; m < 49; m++) {
            float e = __expf(sc[m] - mx);
            sc[m] = e;
            sum += e;
        }
        float inv = 1.f / sum;
        float out[32];
        #pragma unroll
        for (int dd = 0; dd < 32; dd++) out[dd] = 0.f;
        #pragma unroll 7
        for (int m = 0; m < 49; m++) {
            float p = sc[m];
            #pragma unroll
            for (int dd = 0; dd < 32; dd += 4) {
                float4 vf = *(const float4*)&vs[m][dd];
                out[dd]     += p * vf.x;
                out[dd + 1] += p * vf.y;
                out[dd + 2] += p * vf.z;
                out[dd + 3] += p * vf.w;
            }
        }
        size_t ob = (size_t)tok[tid] * C_DIM + cb;
        #pragma unroll
        for (int dd = 0; dd < 32; dd += 4) {
            *(uint2*)(oh + ob + dd) =
                make_uint2(h2pack(out[dd] * inv,     out[dd + 1] * inv),
                           h2pack(out[dd + 2] * inv, out[dd + 3] * inv));
        }
    }
}

// ---------------- launch ----------------
extern "C" void kernel_launch(void* const* d_in, const int* in_sizes, int n_in,
                              void* d_out, int out_size) {
    const float* x      = (const float*)d_in[0];
    const float* g1     = (const float*)d_in[3];
    const float* b1     = (const float*)d_in[4];
    const float* w_qkv  = (const float*)d_in[5];
    const float* b_qkv  = (const float*)d_in[6];
    const float* w_proj = (const float*)d_in[7];
    const float* b_proj = (const float*)d_in[8];
    const float* g2     = (const float*)d_in[9];
    const float* b2     = (const float*)d_in[10];
    const float* w_fc1  = (const float*)d_in[11];
    const float* b_fc1  = (const float*)d_in[12];
    const float* w_fc2  = (const float*)d_in[13];
    const float* b_fc2  = (const float*)d_in[14];
    float* out = (float*)d_out;

    __half *ah, *bh, *wh;
    float *qkv, *x2;
    cudaGetSymbolAddress((void**)&ah,  g_a);
    cudaGetSymbolAddress((void**)&bh,  g_b);
    cudaGetSymbolAddress((void**)&wh,  g_w);
    cudaGetSymbolAddress((void**)&qkv, g_qkv);
    cudaGetSymbolAddress((void**)&x2,  g_x2);

    __half* wqkv_h  = wh;
    __half* wproj_h = wqkv_h  + W_QKV_ELEMS;
    __half* wfc1_h  = wproj_h + W_PROJ_ELEMS;
    __half* wfc2_h  = wfc1_h  + W_FC1_ELEMS;

    cudaFuncSetAttribute(gemm_mma<0>, cudaFuncAttributeMaxDynamicSharedMemorySize, GEMM_SMEM);
    cudaFuncSetAttribute(gemm_mma<1>, cudaFuncAttributeMaxDynamicSharedMemorySize, GEMM_SMEM);
    cudaFuncSetAttribute(gemm_mma<2>, cudaFuncAttributeMaxDynamicSharedMemorySize, GEMM_SMEM);

    const int MT = T_TOKENS / 128;  // 784

    // 0) convert all weights to fp16 (single launch)
    wconv_all_kernel<<<W_TOTAL / 1024, 256>>>(w_qkv, w_proj, w_fc1, w_fc2, wh);
    // 1) LN1 -> fp16
    ln_h_kernel<<<T_TOKENS / 8, 256>>>(x, g1, b1, ah);
    // 2) QKV projection -> fp32
    gemm_mma<0><<<dim3(QKV_DIM / 128, MT), 128, GEMM_SMEM>>>(
        ah, wqkv_h, b_qkv, nullptr, qkv, nullptr, QKV_DIM, C_DIM);
    // 3) window attention -> fp16
    attn_kernel<<<2048 * 8, 64>>>(qkv, ah);
    // 4) proj + residual(x) -> x2
    gemm_mma<1><<<dim3(C_DIM / 128, MT), 128, GEMM_SMEM>>>(
        ah, wproj_h, b_proj, x, x2, nullptr, C_DIM, C_DIM);
    // 5) LN2 -> fp16
    ln_h_kernel<<<T_TOKENS / 8, 256>>>(x2, g2, b2, ah);
    // 6) FC1 + GELU -> fp16
    gemm_mma<2><<<dim3(HID / 128, MT), 128, GEMM_SMEM>>>(
        ah, wfc1_h, b_fc1, nullptr, nullptr, bh, HID, C_DIM);
    // 7) FC2 + residual(x2) -> out
    gemm_mma<1><<<dim3(C_DIM / 128, MT), 128, GEMM_SMEM>>>(
        bh, wfc2_h, b_fc2, x2, out, nullptr, C_DIM, HID);
}

// round 15
// speedup vs baseline: 1.0091x; 1.0091x over previous
#include <cuda_runtime.h>
#include <cuda_fp16.h>
#include <math.h>
#include <stdint.h>

// ---------------- problem constants ----------------
#define T_TOKENS 100352      // 8 * 112 * 112
#define C_DIM    256
#define HID      1024
#define QKV_DIM  768
#define IMG      112
#define WS7      7
#define TOK_PER_IMG 12544

#define W_QKV_ELEMS  (QKV_DIM * C_DIM)
#define W_PROJ_ELEMS (C_DIM * C_DIM)
#define W_FC1_ELEMS  (HID * C_DIM)
#define W_FC2_ELEMS  (C_DIM * HID)
#define W_TOTAL (W_QKV_ELEMS + W_PROJ_ELEMS + W_FC1_ELEMS + W_FC2_ELEMS)

// ---------------- scratch ----------------
__device__ __align__(16) __half g_a  [(size_t)T_TOKENS * C_DIM];
__device__ __align__(16) __half g_b  [(size_t)T_TOKENS * HID];
__device__ __align__(16) __half g_w  [(size_t)W_TOTAL];
__device__ __align__(16) float  g_qkv[(size_t)T_TOKENS * QKV_DIM];
__device__ __align__(16) float  g_x2 [(size_t)T_TOKENS * C_DIM];

// ---------------- helpers ----------------
__device__ __forceinline__ uint32_t smem_u32(const void* p) {
    uint32_t a;
    asm("{ .reg .u64 t; cvta.to.shared.u64 t, %1; cvt.u32.u64 %0, t; }"
        : "=r"(a) : "l"(p));
    return a;
}
__device__ __forceinline__ uint32_t h2pack(float a, float b) {
    __half2 t = __floats2half2_rn(a, b);
    return *reinterpret_cast<uint32_t*>(&t);
}
__device__ __forceinline__ void cp16(uint32_t dst, const void* src) {
    asm volatile("cp.async.cg.shared.global [%0], [%1], 16;"
                 :: "r"(dst), "l"(src) : "memory");
}
__device__ __forceinline__ void cp_commit() {
    asm volatile("cp.async.commit_group;" ::: "memory");
}
__device__ __forceinline__ void cp_wait1() {
    asm volatile("cp.async.wait_group 1;" ::: "memory");
}
__device__ __forceinline__ void cp_wait0() {
    asm volatile("cp.async.wait_group 0;" ::: "memory");
}
#define LDM4(r, addr) \
    asm volatile("ldmatrix.sync.aligned.m8n8.x4.shared.b16 {%0,%1,%2,%3}, [%4];" \
        : "=r"((r)[0]), "=r"((r)[1]), "=r"((r)[2]), "=r"((r)[3]) : "r"(addr))
#define MMA(d, a, b) \
    asm volatile("mma.sync.aligned.m16n8k16.row.col.f32.f16.f16.f32 " \
        "{%0,%1,%2,%3}, {%4,%5,%6,%7}, {%8,%9}, {%0,%1,%2,%3};" \
        : "+f"((d)[0]), "+f"((d)[1]), "+f"((d)[2]), "+f"((d)[3]) \
        : "r"((a)[0]), "r"((a)[1]), "r"((a)[2]), "r"((a)[3]), \
          "r"((b)[0]), "r"((b)[1]))

// ---------------- fused weight convert fp32 -> fp16 (all 4 weights) ----------------
__global__ void wconv_all_kernel(const float* __restrict__ w0,
                                 const float* __restrict__ w1,
                                 const float* __restrict__ w2,
                                 const float* __restrict__ w3,
                                 __half* __restrict__ h) {
    int i = (blockIdx.x * 256 + threadIdx.x) * 4;
    const float* src;
    int off;
    if (i < W_QKV_ELEMS)                                   { src = w0; off = i; }
    else if (i < W_QKV_ELEMS + W_PROJ_ELEMS)               { src = w1; off = i - W_QKV_ELEMS; }
    else if (i < W_QKV_ELEMS + W_PROJ_ELEMS + W_FC1_ELEMS) { src = w2; off = i - W_QKV_ELEMS - W_PROJ_ELEMS; }
    else                                                   { src = w3; off = i - W_QKV_ELEMS - W_PROJ_ELEMS - W_FC1_ELEMS; }
    float4 v = *(const float4*)(src + off);
    *(uint2*)(h + i) = make_uint2(h2pack(v.x, v.y), h2pack(v.z, v.w));
}

// ---------------- LayerNorm -> fp16 ----------------
__global__ void ln_h_kernel(const float* __restrict__ x,
                            const float* __restrict__ gamma,
                            const float* __restrict__ beta,
                            __half* __restrict__ oh) {
    int row  = blockIdx.x * 8 + (threadIdx.x >> 5);
    int lane = threadIdx.x & 31;
    const float4* xr = (const float4*)(x + (size_t)row * C_DIM);
    float4 v0 = xr[lane];
    float4 v1 = xr[lane + 32];
    float s  = v0.x + v0.y + v0.z + v0.w + v1.x + v1.y + v1.z + v1.w;
    float s2 = v0.x*v0.x + v0.y*v0.y + v0.z*v0.z + v0.w*v0.w
             + v1.x*v1.x + v1.y*v1.y + v1.z*v1.z + v1.w*v1.w;
    #pragma unroll
    for (int o = 16; o > 0; o >>= 1) {
        s  += __shfl_xor_sync(0xffffffffu, s,  o);
        s2 += __shfl_xor_sync(0xffffffffu, s2, o);
    }
    float mean = s * (1.f / 256.f);
    float var  = s2 * (1.f / 256.f) - mean * mean;
    float inv  = rsqrtf(var + 1e-5f);

    const float4* gr = (const float4*)gamma;
    const float4* br = (const float4*)beta;
    float4 g0 = gr[lane], g1v = gr[lane + 32];
    float4 b0 = br[lane], b1v = br[lane + 32];
    float o0[4], o1[4];
    o0[0] = (v0.x - mean) * inv * g0.x + b0.x;
    o0[1] = (v0.y - mean) * inv * g0.y + b0.y;
    o0[2] = (v0.z - mean) * inv * g0.z + b0.z;
    o0[3] = (v0.w - mean) * inv * g0.w + b0.w;
    o1[0] = (v1.x - mean) * inv * g1v.x + b1v.x;
    o1[1] = (v1.y - mean) * inv * g1v.y + b1v.y;
    o1[2] = (v1.z - mean) * inv * g1v.z + b1v.z;
    o1[3] = (v1.w - mean) * inv * g1v.w + b1v.w;

    size_t base = (size_t)row * C_DIM;
    *(uint2*)(oh + base + lane * 4)       = make_uint2(h2pack(o0[0], o0[1]), h2pack(o0[2], o0[3]));
    *(uint2*)(oh + base + 128 + lane * 4) = make_uint2(h2pack(o1[0], o1[1]), h2pack(o1[2], o1[3]));
}

// ---------------- mma.sync GEMM: C[M,N] = A[M,K] @ W[N,K]^T ----------------
// 128x128 CTA tile, 4 warps (2m x 2n), warp tile 64x64, BK=64, 2-stage
// cp.async pipeline (72KB smem -> 2 CTA/SM), count-correct tail,
// register fragment double-buffering.
// EPI: 0 = bias -> fp32; 1 = bias + residual -> fp32; 2 = bias + GELU -> fp16
#define ARR_BYTES 18432
#define STG_BYTES 36864
#define GEMM_SMEM (2 * STG_BYTES)

template<int EPI>
__global__ __launch_bounds__(128, 2)
void gemm_mma(const __half* __restrict__ A,
              const __half* __restrict__ W,
              const float* __restrict__ bias,
              const float* __restrict__ res,
              float* __restrict__ outf,
              __half* __restrict__ outh,
              int N, int K) {
    extern __shared__ char smem[];
    uint32_t sb = smem_u32(smem);
    int tid  = threadIdx.x;
    int lane = tid & 31, w = tid >> 5;
    int wm = w >> 1, wn = w & 1;
    int m0 = blockIdx.y * 128, n0 = blockIdx.x * 128;
    const int NCH = K >> 6;

    float acc[4][8][4];
    #pragma unroll
    for (int mt = 0; mt < 4; mt++)
        #pragma unroll
        for (int nt = 0; nt < 8; nt++)
            #pragma unroll
            for (int q = 0; q < 4; q++) acc[mt][nt][q] = 0.f;

    #define ISSUE_CHUNK(ch) do {                                               \
        int k0i = (ch) << 6;                                                   \
        uint32_t stb = sb + ((ch) & 1) * STG_BYTES;                            \
        _Pragma("unroll")                                                      \
        for (int i = 0; i < 16; i++) {                                         \
            int idx = i * 128 + tid;                                           \
            int arr = idx >> 10;                                               \
            int rem = idx & 1023;                                              \
            int r = rem >> 3, c = rem & 7;                                     \
            const __half* s = (arr ? W + (size_t)(n0 + r) * K                  \
                                   : A + (size_t)(m0 + r) * K) + k0i + c * 8;  \
            cp16(stb + arr * ARR_BYTES + r * 144 + c * 16, s);                 \
        }                                                                      \
        cp_commit();                                                           \
    } while (0)

    ISSUE_CHUNK(0);

    int arow = wm * 64 + (lane & 15);
    uint32_t aoff = (uint32_t)arow * 144 + ((lane & 16) ? 16u : 0u);
    int brow = wn * 64 + (lane & 7) + ((lane & 16) ? 8 : 0);
    uint32_t boff = (uint32_t)brow * 144 + ((lane & 8) ? 16u : 0u);

    uint32_t ah[2][4][4], bh[2][8][2];

    #define LOAD_FRAGS(kk_, b_, As_, Ws_) do {                                 \
        uint32_t akb = (kk_) * 32;                                             \
        _Pragma("unroll")                                                      \
        for (int mt = 0; mt < 4; mt++)                                         \
            LDM4(ah[b_][mt], (As_) + aoff + (uint32_t)(mt * 16) * 144 + akb);  \
        _Pragma("unroll")                                                      \
        for (int p = 0; p < 4; p++) {                                          \
            uint32_t t[4];                                                     \
            LDM4(t, (Ws_) + boff + (uint32_t)(p * 16) * 144 + akb);            \
            bh[b_][2*p][0] = t[0]; bh[b_][2*p][1] = t[1];                      \
            bh[b_][2*p+1][0] = t[2]; bh[b_][2*p+1][1] = t[3];                  \
        }                                                                      \
    } while (0)

    for (int ch = 0; ch < NCH; ch++) {
        if (ch + 1 < NCH) { ISSUE_CHUNK(ch + 1); cp_wait1(); }
        else cp_wait0();
        __syncthreads();

        uint32_t As = sb + (ch & 1) * STG_BYTES;
        uint32_t Ws = As + ARR_BYTES;

        LOAD_FRAGS(0, 0, As, Ws);
        #pragma unroll
        for (int kk = 0; kk < 4; kk++) {
            int cur = kk & 1;
            if (kk < 3) LOAD_FRAGS(kk + 1, cur ^ 1, As, Ws);
            #pragma unroll
            for (int mt = 0; mt < 4; mt++)
                #pragma unroll
                for (int nt = 0; nt < 8; nt++)
                    MMA(acc[mt][nt], ah[cur][mt], bh[cur][nt]);
        }
        __syncthreads();
    }

    // ---- epilogue: registers -> global ----
    int lg = lane >> 2, lt = lane & 3;
    #pragma unroll
    for (int mt = 0; mt < 4; mt++) {
        #pragma unroll
        for (int h = 0; h < 2; h++) {
            size_t m = (size_t)(m0 + wm * 64 + mt * 16 + lg + h * 8);
            #pragma unroll
            for (int nt = 0; nt < 8; nt++) {
                int n = n0 + wn * 64 + nt * 8 + lt * 2;
                float2 bv = *(const float2*)(bias + n);
                float v0 = acc[mt][nt][h * 2 + 0] + bv.x;
                float v1 = acc[mt][nt][h * 2 + 1] + bv.y;
                if (EPI == 0) {
                    *(float2*)(outf + m * N + n) = make_float2(v0, v1);
                } else if (EPI == 1) {
                    float2 rr = *(const float2*)(res + m * N + n);
                    *(float2*)(outf + m * N + n) = make_float2(v0 + rr.x, v1 + rr.y);
                } else {
                    v0 = 0.5f * v0 * (1.f + erff(v0 * 0.7071067811865476f));
                    v1 = 0.5f * v1 * (1.f + erff(v1 * 0.7071067811865476f));
                    *(uint32_t*)(outh + m * N + n) = h2pack(v0, v1);
                }
            }
        }
    }
    #undef ISSUE_CHUNK
    #undef LOAD_FRAGS
}

// ---------------- fused window attention (fp32 qkv) -> fp16 ----------------
// R15: 2 heads per 128-thread CTA (more resident warps per scheduler) and the
// q.k dot product split into 4 partial accumulators (serial FFMA chain per
// score row drops 128 -> ~32 cycles). fp32 math order otherwise identical.
__global__ __launch_bounds__(128)
void attn_kernel(const float* __restrict__ qkv,
                 __half* __restrict__ oh) {
    __shared__ float ks[2][49][32];
    __shared__ float vs[2][49][32];
    __shared__ int   tok[49];

    int t    = threadIdx.x;
    int hl   = t >> 6;        // head-local 0/1
    int tid  = t & 63;
    int hp   = blockIdx.x & 3;
    int win  = blockIdx.x >> 2;
    int head = hp * 2 + hl;
    int n    = win >> 8;
    int wrem = win & 255;
    int wr   = wrem >> 4;
    int wc   = wrem & 15;

    if (t < 49) {
        int hh = wr * WS7 + t / 7;
        int ww = wc * WS7 + t % 7;
        tok[t] = n * TOK_PER_IMG + hh * IMG + ww;
    }
    __syncthreads();

    int cb = head * 32;
    for (int i = tid; i < 49 * 8; i += 64) {
        int rowi = i >> 3;
        int c4   = (i & 7) * 4;
        const float* base = qkv + (size_t)tok[rowi] * QKV_DIM;
        *(float4*)&ks[hl][rowi][c4] = *(const float4*)(base + C_DIM     + cb + c4);
        *(float4*)&vs[hl][rowi][c4] = *(const float4*)(base + 2 * C_DIM + cb + c4);
    }
    __syncthreads();

    if (tid < 49) {
        float qr[32];
        const float* qb = qkv + (size_t)tok[tid] * QKV_DIM + cb;
        #pragma unroll
        for (int dd = 0; dd < 32; dd += 4) {
            float4 v = *(const float4*)(qb + dd);
            qr[dd] = v.x; qr[dd + 1] = v.y; qr[dd + 2] = v.z; qr[dd + 3] = v.w;
        }
        const float scale = 0.17677669529663687f;
        float sc[49];
        float mx = -1e30f;
        #pragma unroll 7
        for (int m = 0; m < 49; m++) {
            float d0 = 0.f, d1 = 0.f, d2 = 0.f, d3 = 0.f;
            #pragma unroll
            for (int dd = 0; dd < 32; dd += 4) {
                float4 kf = *(const float4*)&ks[hl][m][dd];
                d0 += qr[dd]     * kf.x;
                d1 += qr[dd + 1] * kf.y;
                d2 += qr[dd + 2] * kf.z;
                d3 += qr[dd + 3] * kf.w;
            }
            float d = ((d0 + d1) + (d2 + d3)) * scale;
            sc[m] = d;
            mx = fmaxf(mx, d);
        }
        float sum = 0.f;
        #pragma unroll
        for (int m = 0; m < 49; m++) {
            float e = __expf(sc[m] - mx);
            sc[m] = e;
            sum += e;
        }
        float inv = 1.f / sum;
        float out[32];
        #pragma unroll
        for (int dd = 0; dd < 32; dd++) out[dd] = 0.f;
        #pragma unroll 7
        for (int m = 0; m < 49; m++) {
            float p = sc[m];
            #pragma unroll
            for (int dd = 0; dd < 32; dd += 4) {
                float4 vf = *(const float4*)&vs[hl][m][dd];
                out[dd]     += p * vf.x;
                out[dd + 1] += p * vf.y;
                out[dd + 2] += p * vf.z;
                out[dd + 3] += p * vf.w;
            }
        }
        size_t ob = (size_t)tok[tid] * C_DIM + cb;
        #pragma unroll
        for (int dd = 0; dd < 32; dd += 4) {
            *(uint2*)(oh + ob + dd) =
                make_uint2(h2pack(out[dd] * inv,     out[dd + 1] * inv),
                           h2pack(out[dd + 2] * inv, out[dd + 3] * inv));
        }
    }
}

// ---------------- launch ----------------
extern "C" void kernel_launch(void* const* d_in, const int* in_sizes, int n_in,
                              void* d_out, int out_size) {
    const float* x      = (const float*)d_in[0];
    const float* g1     = (const float*)d_in[3];
    const float* b1     = (const float*)d_in[4];
    const float* w_qkv  = (const float*)d_in[5];
    const float* b_qkv  = (const float*)d_in[6];
    const float* w_proj = (const float*)d_in[7];
    const float* b_proj = (const float*)d_in[8];
    const float* g2     = (const float*)d_in[9];
    const float* b2     = (const float*)d_in[10];
    const float* w_fc1  = (const float*)d_in[11];
    const float* b_fc1  = (const float*)d_in[12];
    const float* w_fc2  = (const float*)d_in[13];
    const float* b_fc2  = (const float*)d_in[14];
    float* out = (float*)d_out;

    __half *ah, *bh, *wh;
    float *qkv, *x2;
    cudaGetSymbolAddress((void**)&ah,  g_a);
    cudaGetSymbolAddress((void**)&bh,  g_b);
    cudaGetSymbolAddress((void**)&wh,  g_w);
    cudaGetSymbolAddress((void**)&qkv, g_qkv);
    cudaGetSymbolAddress((void**)&x2,  g_x2);

    __half* wqkv_h  = wh;
    __half* wproj_h = wqkv_h  + W_QKV_ELEMS;
    __half* wfc1_h  = wproj_h + W_PROJ_ELEMS;
    __half* wfc2_h  = wfc1_h  + W_FC1_ELEMS;

    cudaFuncSetAttribute(gemm_mma<0>, cudaFuncAttributeMaxDynamicSharedMemorySize, GEMM_SMEM);
    cudaFuncSetAttribute(gemm_mma<1>, cudaFuncAttributeMaxDynamicSharedMemorySize, GEMM_SMEM);
    cudaFuncSetAttribute(gemm_mma<2>, cudaFuncAttributeMaxDynamicSharedMemorySize, GEMM_SMEM);

    const int MT = T_TOKENS / 128;  // 784

    // 0) convert all weights to fp16 (single launch)
    wconv_all_kernel<<<W_TOTAL / 1024, 256>>>(w_qkv, w_proj, w_fc1, w_fc2, wh);
    // 1) LN1 -> fp16
    ln_h_kernel<<<T_TOKENS / 8, 256>>>(x, g1, b1, ah);
    // 2) QKV projection -> fp32
    gemm_mma<0><<<dim3(QKV_DIM / 128, MT), 128, GEMM_SMEM>>>(
        ah, wqkv_h, b_qkv, nullptr, qkv, nullptr, QKV_DIM, C_DIM);
    // 3) window attention -> fp16 (2 heads per CTA)
    attn_kernel<<<2048 * 4, 128>>>(qkv, ah);
    // 4) proj + residual(x) -> x2
    gemm_mma<1><<<dim3(C_DIM / 128, MT), 128, GEMM_SMEM>>>(
        ah, wproj_h, b_proj, x, x2, nullptr, C_DIM, C_DIM);
    // 5) LN2 -> fp16
    ln_h_kernel<<<T_TOKENS / 8, 256>>>(x2, g2, b2, ah);
    // 6) FC1 + GELU -> fp16
    gemm_mma<2><<<dim3(HID / 128, MT), 128, GEMM_SMEM>>>(
        ah, wfc1_h, b_fc1, nullptr, nullptr, bh, HID, C_DIM);
    // 7) FC2 + residual(x2) -> out
    gemm_mma<1><<<dim3(C_DIM / 128, MT), 128, GEMM_SMEM>>>(
        bh, wfc2_h, b_fc2, x2, out, nullptr, C_DIM, HID);
}

// round 16
// speedup vs baseline: 1.1183x; 1.1083x over previous
#include <cuda_runtime.h>
#include <cuda_fp16.h>
#include <math.h>
#include <stdint.h>

// ---------------- problem constants ----------------
#define T_TOKENS 100352      // 8 * 112 * 112
#define C_DIM    256
#define HID      1024
#define QKV_DIM  768
#define IMG      112
#define WS7      7
#define TOK_PER_IMG 12544

#define W_QKV_ELEMS  (QKV_DIM * C_DIM)
#define W_PROJ_ELEMS (C_DIM * C_DIM)
#define W_FC1_ELEMS  (HID * C_DIM)
#define W_FC2_ELEMS  (C_DIM * HID)
#define W_TOTAL (W_QKV_ELEMS + W_PROJ_ELEMS + W_FC1_ELEMS + W_FC2_ELEMS)

// ---------------- scratch ----------------
__device__ __align__(16) __half g_a  [(size_t)T_TOKENS * C_DIM];
__device__ __align__(16) __half g_b  [(size_t)T_TOKENS * HID];
__device__ __align__(16) __half g_w  [(size_t)W_TOTAL];
__device__ __align__(16) float  g_qkv[(size_t)T_TOKENS * QKV_DIM];
__device__ __align__(16) float  g_x2 [(size_t)T_TOKENS * C_DIM];

// ---------------- helpers ----------------
__device__ __forceinline__ uint32_t smem_u32(const void* p) {
    uint32_t a;
    asm("{ .reg .u64 t; cvta.to.shared.u64 t, %1; cvt.u32.u64 %0, t; }"
        : "=r"(a) : "l"(p));
    return a;
}
__device__ __forceinline__ uint32_t h2pack(float a, float b) {
    __half2 t = __floats2half2_rn(a, b);
    return *reinterpret_cast<uint32_t*>(&t);
}
__device__ __forceinline__ void cp16(uint32_t dst, const void* src) {
    asm volatile("cp.async.cg.shared.global [%0], [%1], 16;"
                 :: "r"(dst), "l"(src) : "memory");
}
__device__ __forceinline__ void cp_commit() {
    asm volatile("cp.async.commit_group;" ::: "memory");
}
__device__ __forceinline__ void cp_wait1() {
    asm volatile("cp.async.wait_group 1;" ::: "memory");
}
__device__ __forceinline__ void cp_wait0() {
    asm volatile("cp.async.wait_group 0;" ::: "memory");
}
#define LDM4(r, addr) \
    asm volatile("ldmatrix.sync.aligned.m8n8.x4.shared.b16 {%0,%1,%2,%3}, [%4];" \
        : "=r"((r)[0]), "=r"((r)[1]), "=r"((r)[2]), "=r"((r)[3]) : "r"(addr))
#define MMA(d, a, b) \
    asm volatile("mma.sync.aligned.m16n8k16.row.col.f32.f16.f16.f32 " \
        "{%0,%1,%2,%3}, {%4,%5,%6,%7}, {%8,%9}, {%0,%1,%2,%3};" \
        : "+f"((d)[0]), "+f"((d)[1]), "+f"((d)[2]), "+f"((d)[3]) \
        : "r"((a)[0]), "r"((a)[1]), "r"((a)[2]), "r"((a)[3]), \
          "r"((b)[0]), "r"((b)[1]))

// ---------------- fused weight convert fp32 -> fp16 (all 4 weights) ----------------
__global__ void wconv_all_kernel(const float* __restrict__ w0,
                                 const float* __restrict__ w1,
                                 const float* __restrict__ w2,
                                 const float* __restrict__ w3,
                                 __half* __restrict__ h) {
    int i = (blockIdx.x * 256 + threadIdx.x) * 4;
    const float* src;
    int off;
    if (i < W_QKV_ELEMS)                                   { src = w0; off = i; }
    else if (i < W_QKV_ELEMS + W_PROJ_ELEMS)               { src = w1; off = i - W_QKV_ELEMS; }
    else if (i < W_QKV_ELEMS + W_PROJ_ELEMS + W_FC1_ELEMS) { src = w2; off = i - W_QKV_ELEMS - W_PROJ_ELEMS; }
    else                                                   { src = w3; off = i - W_QKV_ELEMS - W_PROJ_ELEMS - W_FC1_ELEMS; }
    float4 v = *(const float4*)(src + off);
    *(uint2*)(h + i) = make_uint2(h2pack(v.x, v.y), h2pack(v.z, v.w));
}

// ---------------- LayerNorm -> fp16 ----------------
__global__ void ln_h_kernel(const float* __restrict__ x,
                            const float* __restrict__ gamma,
                            const float* __restrict__ beta,
                            __half* __restrict__ oh) {
    int row  = blockIdx.x * 8 + (threadIdx.x >> 5);
    int lane = threadIdx.x & 31;
    const float4* xr = (const float4*)(x + (size_t)row * C_DIM);
    float4 v0 = xr[lane];
    float4 v1 = xr[lane + 32];
    float s  = v0.x + v0.y + v0.z + v0.w + v1.x + v1.y + v1.z + v1.w;
    float s2 = v0.x*v0.x + v0.y*v0.y + v0.z*v0.z + v0.w*v0.w
             + v1.x*v1.x + v1.y*v1.y + v1.z*v1.z + v1.w*v1.w;
    #pragma unroll
    for (int o = 16; o > 0; o >>= 1) {
        s  += __shfl_xor_sync(0xffffffffu, s,  o);
        s2 += __shfl_xor_sync(0xffffffffu, s2, o);
    }
    float mean = s * (1.f / 256.f);
    float var  = s2 * (1.f / 256.f) - mean * mean;
    float inv  = rsqrtf(var + 1e-5f);

    const float4* gr = (const float4*)gamma;
    const float4* br = (const float4*)beta;
    float4 g0 = gr[lane], g1v = gr[lane + 32];
    float4 b0 = br[lane], b1v = br[lane + 32];
    float o0[4], o1[4];
    o0[0] = (v0.x - mean) * inv * g0.x + b0.x;
    o0[1] = (v0.y - mean) * inv * g0.y + b0.y;
    o0[2] = (v0.z - mean) * inv * g0.z + b0.z;
    o0[3] = (v0.w - mean) * inv * g0.w + b0.w;
    o1[0] = (v1.x - mean) * inv * g1v.x + b1v.x;
    o1[1] = (v1.y - mean) * inv * g1v.y + b1v.y;
    o1[2] = (v1.z - mean) * inv * g1v.z + b1v.z;
    o1[3] = (v1.w - mean) * inv * g1v.w + b1v.w;

    size_t base = (size_t)row * C_DIM;
    *(uint2*)(oh + base + lane * 4)       = make_uint2(h2pack(o0[0], o0[1]), h2pack(o0[2], o0[3]));
    *(uint2*)(oh + base + 128 + lane * 4) = make_uint2(h2pack(o1[0], o1[1]), h2pack(o1[2], o1[3]));
}

// ---------------- mma.sync GEMM: C[M,N] = A[M,K] @ W[N,K]^T ----------------
// 128x128 CTA tile, 4 warps (2m x 2n), warp tile 64x64, BK=64, 2-stage
// cp.async pipeline (72KB smem -> 2 CTA/SM), count-correct tail,
// register fragment double-buffering.
// EPI: 0 = bias -> fp32; 1 = bias + residual -> fp32; 2 = bias + GELU -> fp16
#define ARR_BYTES 18432
#define STG_BYTES 36864
#define GEMM_SMEM (2 * STG_BYTES)

template<int EPI>
__global__ __launch_bounds__(128, 2)
void gemm_mma(const __half* __restrict__ A,
              const __half* __restrict__ W,
              const float* __restrict__ bias,
              const float* __restrict__ res,
              float* __restrict__ outf,
              __half* __restrict__ outh,
              int N, int K) {
    extern __shared__ char smem[];
    uint32_t sb = smem_u32(smem);
    int tid  = threadIdx.x;
    int lane = tid & 31, w = tid >> 5;
    int wm = w >> 1, wn = w & 1;
    int m0 = blockIdx.y * 128, n0 = blockIdx.x * 128;
    const int NCH = K >> 6;

    float acc[4][8][4];
    #pragma unroll
    for (int mt = 0; mt < 4; mt++)
        #pragma unroll
        for (int nt = 0; nt < 8; nt++)
            #pragma unroll
            for (int q = 0; q < 4; q++) acc[mt][nt][q] = 0.f;

    #define ISSUE_CHUNK(ch) do {                                               \
        int k0i = (ch) << 6;                                                   \
        uint32_t stb = sb + ((ch) & 1) * STG_BYTES;                            \
        _Pragma("unroll")                                                      \
        for (int i = 0; i < 16; i++) {                                         \
            int idx = i * 128 + tid;                                           \
            int arr = idx >> 10;                                               \
            int rem = idx & 1023;                                              \
            int r = rem >> 3, c = rem & 7;                                     \
            const __half* s = (arr ? W + (size_t)(n0 + r) * K                  \
                                   : A + (size_t)(m0 + r) * K) + k0i + c * 8;  \
            cp16(stb + arr * ARR_BYTES + r * 144 + c * 16, s);                 \
        }                                                                      \
        cp_commit();                                                           \
    } while (0)

    ISSUE_CHUNK(0);

    int arow = wm * 64 + (lane & 15);
    uint32_t aoff = (uint32_t)arow * 144 + ((lane & 16) ? 16u : 0u);
    int brow = wn * 64 + (lane & 7) + ((lane & 16) ? 8 : 0);
    uint32_t boff = (uint32_t)brow * 144 + ((lane & 8) ? 16u : 0u);

    uint32_t ah[2][4][4], bh[2][8][2];

    #define LOAD_FRAGS(kk_, b_, As_, Ws_) do {                                 \
        uint32_t akb = (kk_) * 32;                                             \
        _Pragma("unroll")                                                      \
        for (int mt = 0; mt < 4; mt++)                                         \
            LDM4(ah[b_][mt], (As_) + aoff + (uint32_t)(mt * 16) * 144 + akb);  \
        _Pragma("unroll")                                                      \
        for (int p = 0; p < 4; p++) {                                          \
            uint32_t t[4];                                                     \
            LDM4(t, (Ws_) + boff + (uint32_t)(p * 16) * 144 + akb);            \
            bh[b_][2*p][0] = t[0]; bh[b_][2*p][1] = t[1];                      \
            bh[b_][2*p+1][0] = t[2]; bh[b_][2*p+1][1] = t[3];                  \
        }                                                                      \
    } while (0)

    for (int ch = 0; ch < NCH; ch++) {
        if (ch + 1 < NCH) { ISSUE_CHUNK(ch + 1); cp_wait1(); }
        else cp_wait0();
        __syncthreads();

        uint32_t As = sb + (ch & 1) * STG_BYTES;
        uint32_t Ws = As + ARR_BYTES;

        LOAD_FRAGS(0, 0, As, Ws);
        #pragma unroll
        for (int kk = 0; kk < 4; kk++) {
            int cur = kk & 1;
            if (kk < 3) LOAD_FRAGS(kk + 1, cur ^ 1, As, Ws);
            #pragma unroll
            for (int mt = 0; mt < 4; mt++)
                #pragma unroll
                for (int nt = 0; nt < 8; nt++)
                    MMA(acc[mt][nt], ah[cur][mt], bh[cur][nt]);
        }
        __syncthreads();
    }

    // ---- epilogue: registers -> global ----
    int lg = lane >> 2, lt = lane & 3;
    #pragma unroll
    for (int mt = 0; mt < 4; mt++) {
        #pragma unroll
        for (int h = 0; h < 2; h++) {
            size_t m = (size_t)(m0 + wm * 64 + mt * 16 + lg + h * 8);
            #pragma unroll
            for (int nt = 0; nt < 8; nt++) {
                int n = n0 + wn * 64 + nt * 8 + lt * 2;
                float2 bv = *(const float2*)(bias + n);
                float v0 = acc[mt][nt][h * 2 + 0] + bv.x;
                float v1 = acc[mt][nt][h * 2 + 1] + bv.y;
                if (EPI == 0) {
                    *(float2*)(outf + m * N + n) = make_float2(v0, v1);
                } else if (EPI == 1) {
                    float2 rr = *(const float2*)(res + m * N + n);
                    *(float2*)(outf + m * N + n) = make_float2(v0 + rr.x, v1 + rr.y);
                } else {
                    v0 = 0.5f * v0 * (1.f + erff(v0 * 0.7071067811865476f));
                    v1 = 0.5f * v1 * (1.f + erff(v1 * 0.7071067811865476f));
                    *(uint32_t*)(outh + m * N + n) = h2pack(v0, v1);
                }
            }
        }
    }
    #undef ISSUE_CHUNK
    #undef LOAD_FRAGS
}

// ---------------- fused window attention (fp32 qkv) -> fp16 ----------------
// R16: q.k and p.v in __half2 (HFMA2) — halves the dominant arithmetic and
// smem bytes. K/V converted fp32->half2 at smem fill; softmax stays fp32.
// 2 heads per 128-thread CTA as in R15.
__global__ __launch_bounds__(128)
void attn_kernel(const float* __restrict__ qkv,
                 __half* __restrict__ oh) {
    __shared__ __align__(16) __half2 ks[2][49][16];
    __shared__ __align__(16) __half2 vs[2][49][16];
    __shared__ int tok[49];

    int t    = threadIdx.x;
    int hl   = t >> 6;        // head-local 0/1
    int tid  = t & 63;
    int hp   = blockIdx.x & 3;
    int win  = blockIdx.x >> 2;
    int head = hp * 2 + hl;
    int n    = win >> 8;
    int wrem = win & 255;
    int wr   = wrem >> 4;
    int wc   = wrem & 15;

    if (t < 49) {
        int hh = wr * WS7 + t / 7;
        int ww = wc * WS7 + t % 7;
        tok[t] = n * TOK_PER_IMG + hh * IMG + ww;
    }
    __syncthreads();

    int cb = head * 32;
    for (int i = tid; i < 49 * 8; i += 64) {
        int rowi = i >> 3;
        int c4   = (i & 7) * 4;          // fp32 dims c4..c4+3 -> half2 slots c4/2, c4/2+1
        const float* base = qkv + (size_t)tok[rowi] * QKV_DIM;
        float4 kf = *(const float4*)(base + C_DIM     + cb + c4);
        float4 vf = *(const float4*)(base + 2 * C_DIM + cb + c4);
        *(uint2*)&ks[hl][rowi][c4 >> 1] = make_uint2(h2pack(kf.x, kf.y), h2pack(kf.z, kf.w));
        *(uint2*)&vs[hl][rowi][c4 >> 1] = make_uint2(h2pack(vf.x, vf.y), h2pack(vf.z, vf.w));
    }
    __syncthreads();

    if (tid < 49) {
        __half2 qh[16];
        const float* qb = qkv + (size_t)tok[tid] * QKV_DIM + cb;
        #pragma unroll
        for (int dd = 0; dd < 32; dd += 4) {
            float4 v = *(const float4*)(qb + dd);
            qh[dd >> 1]       = __floats2half2_rn(v.x, v.y);
            qh[(dd >> 1) + 1] = __floats2half2_rn(v.z, v.w);
        }
        const float scale = 0.17677669529663687f;
        const __half2 z = __floats2half2_rn(0.f, 0.f);
        float sc[49];
        float mx = -1e30f;
        #pragma unroll 7
        for (int m = 0; m < 49; m++) {
            const uint4* kr4 = (const uint4*)ks[hl][m];
            __half2 a0 = z, a1 = z, a2 = z, a3 = z;
            #pragma unroll
            for (int q = 0; q < 4; q++) {
                uint4 w = kr4[q];
                a0 = __hfma2(qh[q * 4 + 0], *(__half2*)&w.x, a0);
                a1 = __hfma2(qh[q * 4 + 1], *(__half2*)&w.y, a1);
                a2 = __hfma2(qh[q * 4 + 2], *(__half2*)&w.z, a2);
                a3 = __hfma2(qh[q * 4 + 3], *(__half2*)&w.w, a3);
            }
            float2 f0 = __half22float2(a0), f1 = __half22float2(a1);
            float2 f2 = __half22float2(a2), f3 = __half22float2(a3);
            float d = ((f0.x + f0.y) + (f1.x + f1.y))
                    + ((f2.x + f2.y) + (f3.x + f3.y));
            d *= scale;
            sc[m] = d;
            mx = fmaxf(mx, d);
        }
        float sum = 0.f;
        #pragma unroll
        for (int m = 0; m < 49; m++) {
            float e = __expf(sc[m] - mx);
            sc[m] = e;
            sum += e;
        }
        float inv = 1.f / sum;
        #pragma unroll
        for (int m = 0; m < 49; m++) sc[m] *= inv;   // normalized p, fp32

        __half2 out[16];
        #pragma unroll
        for (int j = 0; j < 16; j++) out[j] = z;
        #pragma unroll 7
        for (int m = 0; m < 49; m++) {
            __half2 ph = __float2half2_rn(sc[m]);
            const uint4* vr4 = (const uint4*)vs[hl][m];
            #pragma unroll
            for (int q = 0; q < 4; q++) {
                uint4 w = vr4[q];
                out[q * 4 + 0] = __hfma2(ph, *(__half2*)&w.x, out[q * 4 + 0]);
                out[q * 4 + 1] = __hfma2(ph, *(__half2*)&w.y, out[q * 4 + 1]);
                out[q * 4 + 2] = __hfma2(ph, *(__half2*)&w.z, out[q * 4 + 2]);
                out[q * 4 + 3] = __hfma2(ph, *(__half2*)&w.w, out[q * 4 + 3]);
            }
        }
        size_t ob = (size_t)tok[tid] * C_DIM + cb;
        #pragma unroll
        for (int j = 0; j < 16; j += 4) {
            *(uint4*)(oh + ob + j * 2) =
                make_uint4(*(uint32_t*)&out[j],     *(uint32_t*)&out[j + 1],
                           *(uint32_t*)&out[j + 2], *(uint32_t*)&out[j + 3]);
        }
    }
}

// ---------------- launch ----------------
extern "C" void kernel_launch(void* const* d_in, const int* in_sizes, int n_in,
                              void* d_out, int out_size) {
    const float* x      = (const float*)d_in[0];
    const float* g1     = (const float*)d_in[3];
    const float* b1     = (const float*)d_in[4];
    const float* w_qkv  = (const float*)d_in[5];
    const float* b_qkv  = (const float*)d_in[6];
    const float* w_proj = (const float*)d_in[7];
    const float* b_proj = (const float*)d_in[8];
    const float* g2     = (const float*)d_in[9];
    const float* b2     = (const float*)d_in[10];
    const float* w_fc1  = (const float*)d_in[11];
    const float* b_fc1  = (const float*)d_in[12];
    const float* w_fc2  = (const float*)d_in[13];
    const float* b_fc2  = (const float*)d_in[14];
    float* out = (float*)d_out;

    __half *ah, *bh, *wh;
    float *qkv, *x2;
    cudaGetSymbolAddress((void**)&ah,  g_a);
    cudaGetSymbolAddress((void**)&bh,  g_b);
    cudaGetSymbolAddress((void**)&wh,  g_w);
    cudaGetSymbolAddress((void**)&qkv, g_qkv);
    cudaGetSymbolAddress((void**)&x2,  g_x2);

    __half* wqkv_h  = wh;
    __half* wproj_h = wqkv_h  + W_QKV_ELEMS;
    __half* wfc1_h  = wproj_h + W_PROJ_ELEMS;
    __half* wfc2_h  = wfc1_h  + W_FC1_ELEMS;

    cudaFuncSetAttribute(gemm_mma<0>, cudaFuncAttributeMaxDynamicSharedMemorySize, GEMM_SMEM);
    cudaFuncSetAttribute(gemm_mma<1>, cudaFuncAttributeMaxDynamicSharedMemorySize, GEMM_SMEM);
    cudaFuncSetAttribute(gemm_mma<2>, cudaFuncAttributeMaxDynamicSharedMemorySize, GEMM_SMEM);

    const int MT = T_TOKENS / 128;  // 784

    // 0) convert all weights to fp16 (single launch)
    wconv_all_kernel<<<W_TOTAL / 1024, 256>>>(w_qkv, w_proj, w_fc1, w_fc2, wh);
    // 1) LN1 -> fp16
    ln_h_kernel<<<T_TOKENS / 8, 256>>>(x, g1, b1, ah);
    // 2) QKV projection -> fp32
    gemm_mma<0><<<dim3(QKV_DIM / 128, MT), 128, GEMM_SMEM>>>(
        ah, wqkv_h, b_qkv, nullptr, qkv, nullptr, QKV_DIM, C_DIM);
    // 3) window attention -> fp16 (2 heads per CTA, half2 math)
    attn_kernel<<<2048 * 4, 128>>>(qkv, ah);
    // 4) proj + residual(x) -> x2
    gemm_mma<1><<<dim3(C_DIM / 128, MT), 128, GEMM_SMEM>>>(
        ah, wproj_h, b_proj, x, x2, nullptr, C_DIM, C_DIM);
    // 5) LN2 -> fp16
    ln_h_kernel<<<T_TOKENS / 8, 256>>>(x2, g2, b2, ah);
    // 6) FC1 + GELU -> fp16
    gemm_mma<2><<<dim3(HID / 128, MT), 128, GEMM_SMEM>>>(
        ah, wfc1_h, b_fc1, nullptr, nullptr, bh, HID, C_DIM);
    // 7) FC2 + residual(x2) -> out
    gemm_mma<1><<<dim3(C_DIM / 128, MT), 128, GEMM_SMEM>>>(
        bh, wfc2_h, b_fc2, x2, out, nullptr, C_DIM, HID);
}